// round 1
// baseline (speedup 1.0000x reference)
#include <cuda_runtime.h>
#include <cuda_bf16.h>
#include <cstddef>

// Collapsed VGGT pipeline:
//   depth[t] = patches[t] . (W_tok @ W_depth)  +  coords[t] . (W_pos @ W_depth)
//            + (b_tok + b_pos) . W_depth + b_depth
// The ragged scatter/gather in the reference is an identity on valid tokens.

#define PATCH_DIM 768
#define EMBED_DIM 256
#define COORD_DIM 3

// scratch: [0..767] = v (W_tok@W_depth), [768..770] = u (W_pos@W_depth), [771] = c
__device__ __align__(16) float g_scratch[772];

__global__ void vggt_prep_kernel(const float* __restrict__ W_tok,
                                 const float* __restrict__ b_tok,
                                 const float* __restrict__ W_pos,
                                 const float* __restrict__ b_pos,
                                 const float* __restrict__ W_depth,
                                 const float* __restrict__ b_depth) {
    int t = threadIdx.x;
    // v[i] = sum_j W_tok[i, j] * W_depth[j]
    for (int i = t; i < PATCH_DIM; i += blockDim.x) {
        const float* row = W_tok + (size_t)i * EMBED_DIM;
        float s = 0.f;
        #pragma unroll 8
        for (int j = 0; j < EMBED_DIM; j++)
            s = fmaf(row[j], W_depth[j], s);
        g_scratch[i] = s;
    }
    // u[k] = sum_j W_pos[k, j] * W_depth[j]
    if (t < COORD_DIM) {
        const float* row = W_pos + (size_t)t * EMBED_DIM;
        float s = 0.f;
        #pragma unroll 8
        for (int j = 0; j < EMBED_DIM; j++)
            s = fmaf(row[j], W_depth[j], s);
        g_scratch[PATCH_DIM + t] = s;
    }
    // c = (b_tok + b_pos) . W_depth + b_depth
    if (t == 0) {
        float s = b_depth[0];
        for (int j = 0; j < EMBED_DIM; j++)
            s = fmaf(b_tok[j] + b_pos[j], W_depth[j], s);
        g_scratch[PATCH_DIM + 3] = s;
    }
}

// One warp per token row. 768 floats = 192 float4 per row; each lane reads
// 6 float4 at stride 32 -> fully coalesced 128B transactions, MLP=6.
__global__ __launch_bounds__(256, 8)
void vggt_dot_kernel(const float4* __restrict__ patches,
                     const float* __restrict__ coords,
                     float* __restrict__ out, int T) {
    int warp = (blockIdx.x * blockDim.x + threadIdx.x) >> 5;
    int lane = threadIdx.x & 31;
    if (warp >= T) return;

    const float4* __restrict__ v4 = (const float4*)g_scratch;   // 192 float4, L1-resident
    const float4* __restrict__ row = patches + (size_t)warp * (PATCH_DIM / 4);

    float s = 0.f;
    #pragma unroll
    for (int k = 0; k < 6; k++) {
        float4 a = row[lane + 32 * k];
        float4 b = v4[lane + 32 * k];
        s = fmaf(a.x, b.x, s);
        s = fmaf(a.y, b.y, s);
        s = fmaf(a.z, b.z, s);
        s = fmaf(a.w, b.w, s);
    }
    if (lane < COORD_DIM)
        s = fmaf(coords[(size_t)warp * COORD_DIM + lane], g_scratch[PATCH_DIM + lane], s);

    #pragma unroll
    for (int off = 16; off; off >>= 1)
        s += __shfl_down_sync(0xffffffffu, s, off);

    if (lane == 0)
        out[warp] = s + g_scratch[PATCH_DIM + 3];
}

extern "C" void kernel_launch(void* const* d_in, const int* in_sizes, int n_in,
                              void* d_out, int out_size) {
    // metadata order: counts, all_coords, all_patches, W_tok, b_tok,
    //                 W_pos, b_pos, W_depth, b_depth
    const float* all_coords  = (const float*)d_in[1];
    const float* all_patches = (const float*)d_in[2];
    const float* W_tok   = (const float*)d_in[3];
    const float* b_tok   = (const float*)d_in[4];
    const float* W_pos   = (const float*)d_in[5];
    const float* b_pos   = (const float*)d_in[6];
    const float* W_depth = (const float*)d_in[7];
    const float* b_depth = (const float*)d_in[8];
    float* out = (float*)d_out;

    int T = out_size;  // depth is [T, 1] fp32

    vggt_prep_kernel<<<1, 256>>>(W_tok, b_tok, W_pos, b_pos, W_depth, b_depth);

    int warps_per_block = 256 / 32;
    int blocks = (T + warps_per_block - 1) / warps_per_block;
    vggt_dot_kernel<<<blocks, 256>>>((const float4*)all_patches, all_coords, out, T);
}

// round 2
// speedup vs baseline: 5.6212x; 5.6212x over previous
#include <cuda_runtime.h>
#include <cuda_bf16.h>
#include <cstddef>

// Collapsed VGGT pipeline:
//   depth[t] = patches[t] . (W_tok @ W_depth)  +  coords[t] . (W_pos @ W_depth)
//            + (b_tok + b_pos) . W_depth + b_depth
// The ragged scatter/gather in the reference is an identity on valid tokens.

#define PATCH_DIM 768
#define EMBED_DIM 256
#define COORD_DIM 3

// scratch: [0..767] = v (W_tok@W_depth), [768..770] = u (W_pos@W_depth), [771] = c
__device__ __align__(16) float g_scratch[772];

// One warp per output element of v/u (772 warps total, fully coalesced reads).
// Warp w < 768      : v[w]   = W_tok[w, :]   . W_depth
// Warp 768..770     : u[w-768] = W_pos[w-768, :] . W_depth
// Warp 771          : c      = (b_tok + b_pos) . W_depth + b_depth
__global__ __launch_bounds__(256)
void vggt_prep_kernel(const float* __restrict__ W_tok,
                      const float* __restrict__ b_tok,
                      const float* __restrict__ W_pos,
                      const float* __restrict__ b_pos,
                      const float* __restrict__ W_depth,
                      const float* __restrict__ b_depth) {
    int w    = (blockIdx.x * blockDim.x + threadIdx.x) >> 5;
    int lane = threadIdx.x & 31;
    if (w > PATCH_DIM + COORD_DIM) return;   // 0..771

    float s = 0.f;
    if (w <= PATCH_DIM + COORD_DIM - 1) {
        // dot of a 256-float row with W_depth, via 2 float4 per lane
        const float* base = (w < PATCH_DIM)
            ? (W_tok + (size_t)w * EMBED_DIM)
            : (W_pos + (size_t)(w - PATCH_DIM) * EMBED_DIM);
        const float4* __restrict__ r4 = (const float4*)base;
        const float4* __restrict__ d4 = (const float4*)W_depth;
        #pragma unroll
        for (int k = 0; k < 2; k++) {
            float4 a = r4[lane + 32 * k];
            float4 b = d4[lane + 32 * k];
            s = fmaf(a.x, b.x, s);
            s = fmaf(a.y, b.y, s);
            s = fmaf(a.z, b.z, s);
            s = fmaf(a.w, b.w, s);
        }
    } else {
        // w == 771: bias term
        #pragma unroll
        for (int k = 0; k < 8; k++) {
            int j = lane + 32 * k;
            s = fmaf(b_tok[j] + b_pos[j], W_depth[j], s);
        }
    }

    #pragma unroll
    for (int off = 16; off; off >>= 1)
        s += __shfl_down_sync(0xffffffffu, s, off);

    if (lane == 0) {
        if (w == PATCH_DIM + COORD_DIM) s += b_depth[0];
        g_scratch[w] = s;
    }
}

// One warp per token row. 768 floats = 192 float4 per row; each lane reads
// 6 float4 at stride 32 -> fully coalesced 128B transactions, MLP=6.
// Patches are streamed (__ldcs, zero reuse); v stays L1-resident (3 KB).
__global__ __launch_bounds__(256, 8)
void vggt_dot_kernel(const float4* __restrict__ patches,
                     const float* __restrict__ coords,
                     float* __restrict__ out, int T) {
    int warp = (blockIdx.x * blockDim.x + threadIdx.x) >> 5;
    int lane = threadIdx.x & 31;
    if (warp >= T) return;

    const float4* __restrict__ v4 = (const float4*)g_scratch;   // L1-resident
    const float4* __restrict__ row = patches + (size_t)warp * (PATCH_DIM / 4);

    float s = 0.f;
    #pragma unroll
    for (int k = 0; k < 6; k++) {
        float4 a = __ldcs(row + lane + 32 * k);
        float4 b = v4[lane + 32 * k];
        s = fmaf(a.x, b.x, s);
        s = fmaf(a.y, b.y, s);
        s = fmaf(a.z, b.z, s);
        s = fmaf(a.w, b.w, s);
    }
    if (lane < COORD_DIM)
        s = fmaf(coords[(size_t)warp * COORD_DIM + lane], g_scratch[PATCH_DIM + lane], s);

    #pragma unroll
    for (int off = 16; off; off >>= 1)
        s += __shfl_down_sync(0xffffffffu, s, off);

    if (lane == 0)
        out[warp] = s + g_scratch[PATCH_DIM + 3];
}

extern "C" void kernel_launch(void* const* d_in, const int* in_sizes, int n_in,
                              void* d_out, int out_size) {
    // metadata order: counts, all_coords, all_patches, W_tok, b_tok,
    //                 W_pos, b_pos, W_depth, b_depth
    const float* all_coords  = (const float*)d_in[1];
    const float* all_patches = (const float*)d_in[2];
    const float* W_tok   = (const float*)d_in[3];
    const float* b_tok   = (const float*)d_in[4];
    const float* W_pos   = (const float*)d_in[5];
    const float* b_pos   = (const float*)d_in[6];
    const float* W_depth = (const float*)d_in[7];
    const float* b_depth = (const float*)d_in[8];
    float* out = (float*)d_out;

    int T = out_size;  // depth is [T, 1] fp32

    // 772 warps needed -> 97 blocks of 8 warps
    int prep_warps  = PATCH_DIM + COORD_DIM + 1;
    int prep_blocks = (prep_warps * 32 + 255) / 256;
    vggt_prep_kernel<<<prep_blocks, 256>>>(W_tok, b_tok, W_pos, b_pos, W_depth, b_depth);

    int warps_per_block = 256 / 32;
    int blocks = (T + warps_per_block - 1) / warps_per_block;
    vggt_dot_kernel<<<blocks, 256>>>((const float4*)all_patches, all_coords, out, T);
}

// round 3
// speedup vs baseline: 5.6284x; 1.0013x over previous
#include <cuda_runtime.h>
#include <cuda_bf16.h>
#include <cstddef>

// Collapsed VGGT pipeline:
//   depth[t] = patches[t] . (W_tok @ W_depth)  +  coords[t] . (W_pos @ W_depth)
//            + (b_tok + b_pos) . W_depth + b_depth
// The ragged scatter/gather in the reference is an identity on valid tokens.

#define PATCH_DIM 768
#define EMBED_DIM 256
#define COORD_DIM 3

// scratch: [0..767] = v (W_tok@W_depth), [768..770] = u (W_pos@W_depth), [771] = c
__device__ __align__(16) float g_scratch[772];

// One warp per output element of v/u (772 warps, fully coalesced reads).
__global__ __launch_bounds__(256)
void vggt_prep_kernel(const float* __restrict__ W_tok,
                      const float* __restrict__ b_tok,
                      const float* __restrict__ W_pos,
                      const float* __restrict__ b_pos,
                      const float* __restrict__ W_depth,
                      const float* __restrict__ b_depth) {
    int w    = (blockIdx.x * blockDim.x + threadIdx.x) >> 5;
    int lane = threadIdx.x & 31;
    if (w > PATCH_DIM + COORD_DIM) return;   // 0..771

    float s = 0.f;
    if (w <= PATCH_DIM + COORD_DIM - 1) {
        const float* base = (w < PATCH_DIM)
            ? (W_tok + (size_t)w * EMBED_DIM)
            : (W_pos + (size_t)(w - PATCH_DIM) * EMBED_DIM);
        const float4* __restrict__ r4 = (const float4*)base;
        const float4* __restrict__ d4 = (const float4*)W_depth;
        #pragma unroll
        for (int k = 0; k < 2; k++) {
            float4 a = r4[lane + 32 * k];
            float4 b = d4[lane + 32 * k];
            s = fmaf(a.x, b.x, s);
            s = fmaf(a.y, b.y, s);
            s = fmaf(a.z, b.z, s);
            s = fmaf(a.w, b.w, s);
        }
    } else {
        #pragma unroll
        for (int k = 0; k < 8; k++) {
            int j = lane + 32 * k;
            s = fmaf(b_tok[j] + b_pos[j], W_depth[j], s);
        }
    }

    #pragma unroll
    for (int off = 16; off; off >>= 1)
        s += __shfl_down_sync(0xffffffffu, s, off);

    if (lane == 0) {
        if (w == PATCH_DIM + COORD_DIM) s += b_depth[0];
        g_scratch[w] = s;
    }
}

// One warp per token row. v lives in SMEM so the ONLY global loads are the
// 6 front-batched patch float4s per lane (MLP_p1=6 within the 32-reg budget
// at full occupancy). sv reads go through the LDS pipe, off the LSU queue.
__global__ __launch_bounds__(256, 8)
void vggt_dot_kernel(const float4* __restrict__ patches,
                     const float* __restrict__ coords,
                     float* __restrict__ out, int T) {
    __shared__ float4 sv[PATCH_DIM / 4];   // 3 KB: v
    __shared__ float  su[4];               // u[0..2], c

    int tid = threadIdx.x;
    if (tid < PATCH_DIM / 4) sv[tid] = ((const float4*)g_scratch)[tid];
    if (tid < 4)             su[tid] = g_scratch[PATCH_DIM + tid];
    __syncthreads();

    int warp = (blockIdx.x * blockDim.x + tid) >> 5;
    int lane = tid & 31;
    if (warp >= T) return;

    const float4* __restrict__ row = patches + (size_t)warp * (PATCH_DIM / 4);

    // Front-batch the entire DRAM stream for this lane.
    float4 a0 = __ldcs(row + lane);
    float4 a1 = __ldcs(row + lane + 32);
    float4 a2 = __ldcs(row + lane + 64);
    float4 a3 = __ldcs(row + lane + 96);
    float4 a4 = __ldcs(row + lane + 128);
    float4 a5 = __ldcs(row + lane + 160);
    float  cv = (lane < COORD_DIM) ? coords[(size_t)warp * COORD_DIM + lane] : 0.f;

    float s0 = 0.f, s1 = 0.f;
    {
        float4 b = sv[lane];
        s0 = fmaf(a0.x, b.x, s0); s1 = fmaf(a0.y, b.y, s1);
        s0 = fmaf(a0.z, b.z, s0); s1 = fmaf(a0.w, b.w, s1);
    }
    {
        float4 b = sv[lane + 32];
        s0 = fmaf(a1.x, b.x, s0); s1 = fmaf(a1.y, b.y, s1);
        s0 = fmaf(a1.z, b.z, s0); s1 = fmaf(a1.w, b.w, s1);
    }
    {
        float4 b = sv[lane + 64];
        s0 = fmaf(a2.x, b.x, s0); s1 = fmaf(a2.y, b.y, s1);
        s0 = fmaf(a2.z, b.z, s0); s1 = fmaf(a2.w, b.w, s1);
    }
    {
        float4 b = sv[lane + 96];
        s0 = fmaf(a3.x, b.x, s0); s1 = fmaf(a3.y, b.y, s1);
        s0 = fmaf(a3.z, b.z, s0); s1 = fmaf(a3.w, b.w, s1);
    }
    {
        float4 b = sv[lane + 128];
        s0 = fmaf(a4.x, b.x, s0); s1 = fmaf(a4.y, b.y, s1);
        s0 = fmaf(a4.z, b.z, s0); s1 = fmaf(a4.w, b.w, s1);
    }
    {
        float4 b = sv[lane + 160];
        s0 = fmaf(a5.x, b.x, s0); s1 = fmaf(a5.y, b.y, s1);
        s0 = fmaf(a5.z, b.z, s0); s1 = fmaf(a5.w, b.w, s1);
    }

    float s = s0 + s1;
    if (lane < COORD_DIM) s = fmaf(cv, su[lane], s);

    #pragma unroll
    for (int off = 16; off; off >>= 1)
        s += __shfl_down_sync(0xffffffffu, s, off);

    if (lane == 0)
        out[warp] = s + su[3];
}

extern "C" void kernel_launch(void* const* d_in, const int* in_sizes, int n_in,
                              void* d_out, int out_size) {
    // metadata order: counts, all_coords, all_patches, W_tok, b_tok,
    //                 W_pos, b_pos, W_depth, b_depth
    const float* all_coords  = (const float*)d_in[1];
    const float* all_patches = (const float*)d_in[2];
    const float* W_tok   = (const float*)d_in[3];
    const float* b_tok   = (const float*)d_in[4];
    const float* W_pos   = (const float*)d_in[5];
    const float* b_pos   = (const float*)d_in[6];
    const float* W_depth = (const float*)d_in[7];
    const float* b_depth = (const float*)d_in[8];
    float* out = (float*)d_out;

    int T = out_size;  // depth is [T, 1] fp32

    int prep_warps  = PATCH_DIM + COORD_DIM + 1;      // 772
    int prep_blocks = (prep_warps * 32 + 255) / 256;  // 97
    vggt_prep_kernel<<<prep_blocks, 256>>>(W_tok, b_tok, W_pos, b_pos, W_depth, b_depth);

    int warps_per_block = 256 / 32;
    int blocks = (T + warps_per_block - 1) / warps_per_block;
    vggt_dot_kernel<<<blocks, 256>>>((const float4*)all_patches, all_coords, out, T);
}